// round 1
// baseline (speedup 1.0000x reference)
#include <cuda_runtime.h>
#include <cuda_bf16.h>

// Embedding gather: out[token, :] = table[ids[token], :]
// ids: [32*8192] int32, table: [256,256] f32, out: [32*8192, 256] f32.
// 256 floats per row = 64 float4 per row. One float4 per thread.

static constexpr int TOKENS    = 32 * 8192;   // 262144
static constexpr int EMBED     = 256;
static constexpr int VEC_PER_ROW = EMBED / 4; // 64 float4 per row

__global__ __launch_bounds__(256)
void embed_gather_kernel(const int* __restrict__ ids,
                         const float4* __restrict__ table4,
                         float4* __restrict__ out4)
{
    // Each thread writes one float4 of one token row.
    long long gtid = (long long)blockIdx.x * blockDim.x + threadIdx.x;
    // total float4 elements = TOKENS * 64 = 16,777,216; grid sized exactly.
    int token = (int)(gtid >> 6);        // gtid / 64
    int col4  = (int)(gtid & 63);        // gtid % 64

    int row = __ldg(&ids[token]);        // 64 threads share this -> L1 broadcast
    out4[gtid] = table4[(long long)row * VEC_PER_ROW + col4];
}

extern "C" void kernel_launch(void* const* d_in, const int* in_sizes, int n_in,
                              void* d_out, int out_size)
{
    const int*    ids    = (const int*)d_in[0];     // [32, 8192] int32
    const float*  table  = (const float*)d_in[1];   // [256, 256] f32
    float*        out    = (float*)d_out;           // [32, 8192, 256] f32

    const long long total_vec4 = (long long)TOKENS * VEC_PER_ROW; // 16,777,216
    const int threads = 256;
    const int blocks  = (int)(total_vec4 / threads);              // 65536

    embed_gather_kernel<<<blocks, threads>>>(
        ids, (const float4*)table, (float4*)out);
}

// round 2
// speedup vs baseline: 1.5436x; 1.5436x over previous
#include <cuda_runtime.h>
#include <cuda_bf16.h>

// Embedding gather: out[token, :] = table[ids[token], :]
// ids: [32*8192] int32, table: [256,256] f32, out: [32*8192, 256] f32.
//
// Store-bandwidth-bound: 268 MB of output writes. Strategy: 4 independent
// gather->store chains per thread (grid-strided) to raise MLP, streaming
// stores (.cs) to keep the 256 KB table resident in L2, fully coalesced
// 16B accesses throughout.

static constexpr int       TOKENS       = 32 * 8192;          // 262144
static constexpr int       EMBED        = 256;
static constexpr int       VEC_PER_ROW  = EMBED / 4;          // 64 float4 per row
static constexpr long long TOTAL_VEC4   = (long long)TOKENS * VEC_PER_ROW; // 16,777,216
static constexpr int       ITEMS        = 4;                  // chains per thread

__global__ __launch_bounds__(256)
void embed_gather_kernel(const int* __restrict__ ids,
                         const float4* __restrict__ table4,
                         float4* __restrict__ out4)
{
    const long long NT   = TOTAL_VEC4 / ITEMS;                 // threads total
    long long       gtid = (long long)blockIdx.x * blockDim.x + threadIdx.x;

    long long g[ITEMS];
    int       tok[ITEMS];
    float4    v[ITEMS];

    // Batch the index loads (independent, L1-broadcast across 64 threads).
    #pragma unroll
    for (int k = 0; k < ITEMS; k++) {
        g[k]   = gtid + (long long)k * NT;
        tok[k] = __ldg(&ids[g[k] >> 6]);
    }

    // Batch the table loads (independent -> MLP=4; table lives in L1/L2).
    #pragma unroll
    for (int k = 0; k < ITEMS; k++) {
        v[k] = __ldg(&table4[(long long)tok[k] * VEC_PER_ROW + (g[k] & 63)]);
    }

    // Streaming stores: don't let 268 MB of writes thrash the table out of L2.
    #pragma unroll
    for (int k = 0; k < ITEMS; k++) {
        __stcs(&out4[g[k]], v[k]);
    }
}

extern "C" void kernel_launch(void* const* d_in, const int* in_sizes, int n_in,
                              void* d_out, int out_size)
{
    const int*   ids   = (const int*)d_in[0];    // [32, 8192] int32
    const float* table = (const float*)d_in[1];  // [256, 256] f32
    float*       out   = (float*)d_out;          // [32, 8192, 256] f32

    const int threads = 256;
    const int blocks  = (int)(TOTAL_VEC4 / ITEMS / threads);   // 16384

    embed_gather_kernel<<<blocks, threads>>>(
        ids, (const float4*)table, (float4*)out);
}